// round 4
// baseline (speedup 1.0000x reference)
#include <cuda_runtime.h>
#include <cstdint>

// LeakageNlinCore as a dense M=32768, N=128, K=128 tf32 GEMM (mma.sync path,
// since this toolchain lowers PTX to .target sm_103 without the 'a' feature
// set, making tcgen05 unavailable).
//
// F[t,k] : k<64 -> fr_k = (xr^2+xi^2)*xr ; k>=64 -> fi_{k-64}
// G[n,k] : n=2c+o, weight on F[k] (0 when source channel j == c)
// out[t,n] = sum_k F[t,k] * G[n,k]

#define NTHREADS   256
#define ROWS_WARP  32     // 2 m16 tiles per warp
#define ROWS_CTA   256    // 8 warps * 32 rows
#define KDIM       128
#define NOUT       128
#define STRIDE     132    // padded row stride (floats): banks (4*row+col)%32

// smem: Fs [256][132] then Gs [128][132]
#define FS_FLOATS  (ROWS_CTA * STRIDE)
#define GS_FLOATS  (NOUT * STRIDE)
#define SMEM_BYTES ((FS_FLOATS + GS_FLOATS) * 4)

__device__ __forceinline__ uint32_t f2tf32(float f) {
    uint32_t r;
    asm("cvt.rna.tf32.f32 %0, %1;" : "=r"(r) : "f"(f));
    return r;
}

__device__ __forceinline__ void mma_16x8x8(float& d0, float& d1, float& d2, float& d3,
                                           uint32_t a0, uint32_t a1, uint32_t a2, uint32_t a3,
                                           uint32_t b0, uint32_t b1) {
    asm volatile(
        "mma.sync.aligned.m16n8k8.row.col.f32.tf32.tf32.f32 "
        "{%0,%1,%2,%3}, {%4,%5,%6,%7}, {%8,%9}, {%0,%1,%2,%3};"
        : "+f"(d0), "+f"(d1), "+f"(d2), "+f"(d3)
        : "r"(a0), "r"(a1), "r"(a2), "r"(a3), "r"(b0), "r"(b1));
}

__global__ void __launch_bounds__(NTHREADS, 1)
leakage_mma_kernel(const float* __restrict__ x, const float* __restrict__ W,
                   float* __restrict__ out) {
    extern __shared__ float smem[];
    float* Fs = smem;               // [256][132]
    float* Gs = smem + FS_FLOATS;   // [128][132]

    const int tid = threadIdx.x;
    const int wid = tid >> 5;
    const int lid = tid & 31;
    const int t0 = blockIdx.x * ROWS_CTA;

    // ---- Stage G: G[n][k] from W, tf32-rounded, LOO expansion inline ----
    for (int i = tid; i < NOUT * KDIM; i += NTHREADS) {
        int n = i >> 7, k = i & 127;
        int c = n >> 1, o = n & 1;
        int j = k & 63, half = k >> 6;
        float g = 0.0f;
        if (j != c) {
            int p = (j < c) ? j : (j - 1);
            g = W[(c * 2 + o) * 126 + half * 63 + p];
        }
        ((uint32_t*)Gs)[n * STRIDE + k] = f2tf32(g);
    }

    // ---- Stage F: fused nonlinearity, tf32-rounded ----
    // Each item = (token m, channel pair cp). float4 = (xr0, xi0, xr1, xi1).
    const float4* xb = (const float4*)(x + (size_t)t0 * KDIM);
    for (int i = tid; i < ROWS_CTA * 32; i += NTHREADS) {
        int m = i >> 5, cp = i & 31;
        float4 v = xb[m * 32 + cp];
        float amp0 = v.x * v.x + v.y * v.y;
        float amp1 = v.z * v.z + v.w * v.w;
        uint32_t fr0 = f2tf32(amp0 * v.x), fi0 = f2tf32(amp0 * v.y);
        uint32_t fr1 = f2tf32(amp1 * v.z), fi1 = f2tf32(amp1 * v.w);
        int c0 = cp * 2;
        uint32_t* rowp = (uint32_t*)(Fs + m * STRIDE);
        // fr -> cols [0,64), fi -> cols [64,128)
        *(uint2*)(rowp + c0) = make_uint2(fr0, fr1);
        *(uint2*)(rowp + 64 + c0) = make_uint2(fi0, fi1);
    }
    __syncthreads();

    // ---- Main GEMM: each warp computes rows [wid*32, wid*32+32) x all 128 n ----
    const int g = lid >> 2;    // group id 0..7
    const int tg = lid & 3;    // thread-in-group 0..3

    float acc[2][16][4];
#pragma unroll
    for (int mt = 0; mt < 2; mt++)
#pragma unroll
        for (int nb = 0; nb < 16; nb++)
#pragma unroll
            for (int q = 0; q < 4; q++) acc[mt][nb][q] = 0.0f;

    const uint32_t* Fu = (const uint32_t*)Fs;
    const uint32_t* Gu = (const uint32_t*)Gs;
    const int rb0 = wid * ROWS_WARP + g;   // m-tile 0 row for this thread
    const uint32_t* fa0 = Fu + rb0 * STRIDE + tg;
    const uint32_t* fa1 = Fu + (rb0 + 8) * STRIDE + tg;
    const uint32_t* fa2 = Fu + (rb0 + 16) * STRIDE + tg;
    const uint32_t* fa3 = Fu + (rb0 + 24) * STRIDE + tg;
    const uint32_t* gb = Gu + g * STRIDE + tg;

#pragma unroll
    for (int ks = 0; ks < 16; ks++) {
        const int k0 = ks * 8;
        // A fragments for both m-tiles (row-major m16k8)
        uint32_t a00 = fa0[k0],     a01 = fa1[k0];
        uint32_t a02 = fa0[k0 + 4], a03 = fa1[k0 + 4];
        uint32_t a10 = fa2[k0],     a11 = fa3[k0];
        uint32_t a12 = fa2[k0 + 4], a13 = fa3[k0 + 4];
        const uint32_t* gp = gb + k0;
#pragma unroll
        for (int nb = 0; nb < 16; nb++) {
            // B fragment (col-major k8n8): b0 = G[nb*8+g][k0+tg], b1 = +4
            uint32_t b0 = gp[0];
            uint32_t b1 = gp[4];
            gp += 8 * STRIDE;
            mma_16x8x8(acc[0][nb][0], acc[0][nb][1], acc[0][nb][2], acc[0][nb][3],
                       a00, a01, a02, a03, b0, b1);
            mma_16x8x8(acc[1][nb][0], acc[1][nb][1], acc[1][nb][2], acc[1][nb][3],
                       a10, a11, a12, a13, b0, b1);
        }
    }

    // ---- Epilogue: c0/c1 -> (row g, cols 2tg,2tg+1), c2/c3 -> row g+8 ----
#pragma unroll
    for (int mt = 0; mt < 2; mt++) {
        int r0 = t0 + wid * ROWS_WARP + mt * 16 + g;
        float* o0 = out + (size_t)r0 * NOUT;
        float* o1 = o0 + 8 * NOUT;
#pragma unroll
        for (int nb = 0; nb < 16; nb++) {
            int cc = nb * 8 + tg * 2;
            *(float2*)(o0 + cc) = make_float2(acc[mt][nb][0], acc[mt][nb][1]);
            *(float2*)(o1 + cc) = make_float2(acc[mt][nb][2], acc[mt][nb][3]);
        }
    }
}

extern "C" void kernel_launch(void* const* d_in, const int* in_sizes, int n_in,
                              void* d_out, int out_size) {
    const float* x = (const float*)d_in[0];  // [B,S,C,2] fp32
    const float* W = (const float*)d_in[1];  // [C,2,126] fp32
    float* out = (float*)d_out;              // [B,S,C,2] fp32

    int tokens = in_sizes[0] / KDIM;         // B*S = 32768
    int nblocks = tokens / ROWS_CTA;         // 128

    cudaFuncSetAttribute(leakage_mma_kernel,
                         cudaFuncAttributeMaxDynamicSharedMemorySize, SMEM_BYTES);
    leakage_mma_kernel<<<nblocks, NTHREADS, SMEM_BYTES>>>(x, W, out);
}

// round 5
// speedup vs baseline: 1.6091x; 1.6091x over previous
#include <cuda_runtime.h>
#include <cstdint>

// LeakageNlinCore as dense M=32768, N=128, K=128 tf32 GEMM via mma.sync.
// Round-5 structure:
//  - Pre-kernel packs G into mma B-fragment order (Gpack). Main kernel keeps
//    each warp's B slice (16 n-columns x K=128) in 64 registers, loaded once
//    with 16 coalesced LDG.128. No G smem, no B LDS in the mainloop.
//  - Each CTA owns 256 rows = 4 tiles of 64 rows, double-buffered F smem,
//    next tile's global loads issued before the current mainloop.

#define NTHREADS 256
#define TILE_M   64
#define TILES    4
#define ROWS_CTA (TILE_M * TILES)   // 256
#define KDIM     128
#define NOUT     128
#define STRIDE   132                // padded F row stride (floats)

#define XS_FLOATS (TILE_M * STRIDE)            // one buffer
#define SMEM_BYTES (2 * XS_FLOATS * 4)         // 67584 B

// Fragment-ordered packed G: [wid(8)][j4(16)][lane(32)] float4
__device__ float4 Gpack[8 * 16 * 32];

__device__ __forceinline__ uint32_t f2tf32(float f) {
    uint32_t r;
    asm("cvt.rna.tf32.f32 %0, %1;" : "=r"(r) : "f"(f));
    return r;
}

__device__ __forceinline__ void mma_16x8x8(float& d0, float& d1, float& d2, float& d3,
                                           uint32_t a0, uint32_t a1, uint32_t a2, uint32_t a3,
                                           uint32_t b0, uint32_t b1) {
    asm volatile(
        "mma.sync.aligned.m16n8k8.row.col.f32.tf32.tf32.f32 "
        "{%0,%1,%2,%3}, {%4,%5,%6,%7}, {%8,%9}, {%0,%1,%2,%3};"
        : "+f"(d0), "+f"(d1), "+f"(d2), "+f"(d3)
        : "r"(a0), "r"(a1), "r"(a2), "r"(a3), "r"(b0), "r"(b1));
}

// ---- Pre-kernel: LOO-expand W into B-fragment-ordered Gpack --------------
// Value j (0..63) of warp-slot (wid, lane=(g,tg)):
//   nb = j>>5, ks = (j>>1)&15, h = j&1
//   n  = wid*16 + nb*8 + g,  k = ks*8 + tg + 4*h
__global__ void g_pack_kernel(const float* __restrict__ W) {
    int idx = blockIdx.x * blockDim.x + threadIdx.x;   // 0..4095
    int wid = idx >> 9;
    int j4 = (idx >> 5) & 15;
    int lane = idx & 31;
    int g = lane >> 2, tg = lane & 3;
    float4 v;
    float* pv = (float*)&v;
#pragma unroll
    for (int e = 0; e < 4; e++) {
        int j = j4 * 4 + e;
        int nb = j >> 5, ks = (j >> 1) & 15, h = j & 1;
        int n = wid * 16 + nb * 8 + g;
        int k = ks * 8 + tg + 4 * h;
        int c = n >> 1, o = n & 1;
        int jj = k & 63, half = k >> 6;
        float gg = 0.0f;
        if (jj != c) {
            int p = (jj < c) ? jj : (jj - 1);
            gg = W[(c * 2 + o) * 126 + half * 63 + p];
        }
        pv[e] = __uint_as_float(f2tf32(gg));
    }
    Gpack[idx] = v;
}

// ---- Main kernel ----------------------------------------------------------
__global__ void __launch_bounds__(NTHREADS, 1)
leakage_main_kernel(const float* __restrict__ x, float* __restrict__ out) {
    extern __shared__ float xs[];   // [2][64][132]

    const int tid = threadIdx.x;
    const int wid = tid >> 5;
    const int lid = tid & 31;
    const int g = lid >> 2;
    const int tg = lid & 3;
    const size_t t0 = (size_t)blockIdx.x * ROWS_CTA;

    // ---- B slice for this warp: 64 regs, 16 coalesced LDG.128 ----
    float b[2][16][2];
    {
        const float4* gp = Gpack + wid * 512 + lid;
#pragma unroll
        for (int j4 = 0; j4 < 16; j4++) {
            float4 q = gp[j4 * 32];
#pragma unroll
            for (int e = 0; e < 4; e++) {
                const int j = j4 * 4 + e;
                const int nb = j >> 5, ks = (j >> 1) & 15, h = j & 1;
                float val = (e == 0) ? q.x : (e == 1) ? q.y : (e == 2) ? q.z : q.w;
                b[nb][ks][h] = val;
            }
        }
    }

    // ---- Stage tile 0 into regs ----
    float4 r[8];
    {
        const float4* xb = (const float4*)(x + t0 * KDIM);
#pragma unroll
        for (int it = 0; it < 8; it++)
            r[it] = xb[(wid + it * 8) * 32 + lid];
    }

#pragma unroll 1
    for (int t = 0; t < TILES; t++) {
        float* buf = xs + (t & 1) * XS_FLOATS;

        // ---- Transform r -> F, store to smem ----
        // item it: row m = wid + it*8, channel pair cp = lid.
#pragma unroll
        for (int it = 0; it < 8; it++) {
            float4 v = r[it];
            float amp0 = v.x * v.x + v.y * v.y;
            float amp1 = v.z * v.z + v.w * v.w;
            uint32_t fr0 = f2tf32(amp0 * v.x), fi0 = f2tf32(amp0 * v.y);
            uint32_t fr1 = f2tf32(amp1 * v.z), fi1 = f2tf32(amp1 * v.w);
            uint32_t* rowp = (uint32_t*)(buf + (wid + it * 8) * STRIDE);
            int c0 = lid * 2;
            *(uint2*)(rowp + c0) = make_uint2(fr0, fr1);          // fr -> [0,64)
            *(uint2*)(rowp + 64 + c0) = make_uint2(fi0, fi1);     // fi -> [64,128)
        }
        __syncthreads();

        // ---- Issue next tile's global loads (latency hides behind mainloop) ----
        if (t + 1 < TILES) {
            const float4* xb = (const float4*)(x + (t0 + (size_t)(t + 1) * TILE_M) * KDIM);
#pragma unroll
            for (int it = 0; it < 8; it++)
                r[it] = xb[(wid + it * 8) * 32 + lid];
        }

        // ---- Mainloop: warp covers 64 rows x its 16 n-cols ----
        float acc[4][2][4];
#pragma unroll
        for (int mt = 0; mt < 4; mt++)
#pragma unroll
            for (int nb = 0; nb < 2; nb++)
#pragma unroll
                for (int q = 0; q < 4; q++) acc[mt][nb][q] = 0.0f;

        const uint32_t* F = (const uint32_t*)buf;
#pragma unroll
        for (int ks = 0; ks < 16; ks++) {
            const int k0 = ks * 8 + tg;
            uint32_t a[4][4];
#pragma unroll
            for (int mt = 0; mt < 4; mt++) {
                const uint32_t* f0 = F + (mt * 16 + g) * STRIDE + k0;
                const uint32_t* f1 = F + (mt * 16 + g + 8) * STRIDE + k0;
                a[mt][0] = f0[0];
                a[mt][1] = f1[0];
                a[mt][2] = f0[4];
                a[mt][3] = f1[4];
            }
#pragma unroll
            for (int mt = 0; mt < 4; mt++) {
                uint32_t b00 = __float_as_uint(b[0][ks][0]);
                uint32_t b01 = __float_as_uint(b[0][ks][1]);
                uint32_t b10 = __float_as_uint(b[1][ks][0]);
                uint32_t b11 = __float_as_uint(b[1][ks][1]);
                mma_16x8x8(acc[mt][0][0], acc[mt][0][1], acc[mt][0][2], acc[mt][0][3],
                           a[mt][0], a[mt][1], a[mt][2], a[mt][3], b00, b01);
                mma_16x8x8(acc[mt][1][0], acc[mt][1][1], acc[mt][1][2], acc[mt][1][3],
                           a[mt][0], a[mt][1], a[mt][2], a[mt][3], b10, b11);
            }
        }

        // ---- Epilogue: store this tile's warp slice ----
        const size_t rbase = t0 + (size_t)t * TILE_M;
#pragma unroll
        for (int mt = 0; mt < 4; mt++) {
#pragma unroll
            for (int nb = 0; nb < 2; nb++) {
                const int col = wid * 16 + nb * 8 + tg * 2;
                float* o0 = out + (rbase + mt * 16 + g) * NOUT + col;
                *(float2*)o0 = make_float2(acc[mt][nb][0], acc[mt][nb][1]);
                *(float2*)(o0 + 8 * NOUT) = make_float2(acc[mt][nb][2], acc[mt][nb][3]);
            }
        }
        // No second sync: next transform writes the OTHER buffer; the sync at
        // the top of iteration t+1 orders reuse of this buffer at t+2.
        __syncthreads();
    }
}

extern "C" void kernel_launch(void* const* d_in, const int* in_sizes, int n_in,
                              void* d_out, int out_size) {
    const float* x = (const float*)d_in[0];  // [B,S,C,2] fp32
    const float* W = (const float*)d_in[1];  // [C,2,126] fp32
    float* out = (float*)d_out;              // [B,S,C,2] fp32

    int tokens = in_sizes[0] / KDIM;         // 32768
    int nblocks = tokens / ROWS_CTA;         // 128

    g_pack_kernel<<<16, 256>>>(W);
    cudaFuncSetAttribute(leakage_main_kernel,
                         cudaFuncAttributeMaxDynamicSharedMemorySize, SMEM_BYTES);
    leakage_main_kernel<<<nblocks, NTHREADS, SMEM_BYTES>>>(x, out);
}